// round 1
// baseline (speedup 1.0000x reference)
#include <cuda_runtime.h>
#include <math.h>

// ---------------------------------------------------------------------------
// TransformerEncoder block: H=1024, S1=150 (149 tokens + cls), B=128,
// banded attention (half-width 20, cls row global).
// Round 1: correct fp32 baseline. GEMMs are classic 128x128x8 SIMT tiles.
// ---------------------------------------------------------------------------

#define H   1024
#define S1  150
#define NB  128
#define NR  (S1 * NB)      // 19200 rows, r = b*S1 + s  (x is (B,S1,H) flattened)
#define WIN 20

// Scratch (allocation-free: device globals)
__device__ float g_pe [S1 * H];
__device__ float g_x  [NR * H];          // post-LN input x
__device__ float g_qkv[NR * 3 * H];
__device__ float g_att[NR * H];          // attention output (pre w_o)
__device__ float g_sa [NR * H];          // w_o projection
__device__ float g_zsa[NR * H];          // LN(x + sa)
__device__ float g_h1 [NR * H];          // gelu(zsa @ w_m1 + b_m1)

// ---------------------------------------------------------------------------
// Kernel 0: positional encoding table (fp64 for exact sin/cos arguments)
// ---------------------------------------------------------------------------
__global__ void pe_kernel() {
    int s = blockIdx.x;
    double pos = 6.283185307179586476925286766559 * (double)s;  // 2*pi*s
    for (int h = threadIdx.x; h < H; h += blockDim.x) {
        int e = h & ~1;
        double dv = exp((double)e * (-log(10000.0) / (double)H));
        double a = pos * dv;
        g_pe[s * H + h] = (float)((h & 1) ? cos(a) : sin(a));
    }
}

// ---------------------------------------------------------------------------
// Block reduce helper (256 threads = 8 warps): sum of two accumulators
// ---------------------------------------------------------------------------
__device__ __forceinline__ float2 block_reduce2(float a, float b, float* sh) {
    int lane = threadIdx.x & 31, wid = threadIdx.x >> 5;
#pragma unroll
    for (int o = 16; o; o >>= 1) {
        a += __shfl_xor_sync(0xffffffffu, a, o);
        b += __shfl_xor_sync(0xffffffffu, b, o);
    }
    if (lane == 0) { sh[wid] = a; sh[8 + wid] = b; }
    __syncthreads();
    if (threadIdx.x == 0) {
        float s = 0.f, q = 0.f;
#pragma unroll
        for (int i = 0; i < 8; i++) { s += sh[i]; q += sh[8 + i]; }
        sh[0] = s; sh[8] = q;
    }
    __syncthreads();
    return make_float2(sh[0], sh[8]);
}

// ---------------------------------------------------------------------------
// Kernel 1: x = LayerNorm(concat(cls, z^T) + pe) ; one block per row r
// ---------------------------------------------------------------------------
__global__ void build_ln_kernel(const float* __restrict__ z,
                                const float* __restrict__ cls,
                                const float* __restrict__ lg,
                                const float* __restrict__ lb) {
    __shared__ float sh[16];
    int r = blockIdx.x;
    int b = r / S1, s = r % S1;
    int tid = threadIdx.x;
    const float* src = (s == 0) ? cls : (z + ((size_t)(s - 1) * NB + b) * H);

    float v[4];
    float sum = 0.f, sq = 0.f;
#pragma unroll
    for (int i = 0; i < 4; i++) {
        int h = tid + i * 256;
        float val = src[h] + g_pe[s * H + h];
        v[i] = val; sum += val; sq += val * val;
    }
    float2 t = block_reduce2(sum, sq, sh);
    float mean = t.x * (1.f / H);
    float var  = t.y * (1.f / H) - mean * mean;
    float rstd = rsqrtf(var + 1e-5f);
#pragma unroll
    for (int i = 0; i < 4; i++) {
        int h = tid + i * 256;
        g_x[(size_t)r * H + h] = (v[i] - mean) * rstd * lg[h] + lb[h];
    }
}

// ---------------------------------------------------------------------------
// Kernel: zsa = LayerNorm(x + sa)
// ---------------------------------------------------------------------------
__global__ void res_ln_kernel(const float* __restrict__ lg,
                              const float* __restrict__ lb) {
    __shared__ float sh[16];
    int r = blockIdx.x;
    int tid = threadIdx.x;
    float v[4];
    float sum = 0.f, sq = 0.f;
#pragma unroll
    for (int i = 0; i < 4; i++) {
        int h = tid + i * 256;
        size_t idx = (size_t)r * H + h;
        float val = g_x[idx] + g_sa[idx];
        v[i] = val; sum += val; sq += val * val;
    }
    float2 t = block_reduce2(sum, sq, sh);
    float mean = t.x * (1.f / H);
    float var  = t.y * (1.f / H) - mean * mean;
    float rstd = rsqrtf(var + 1e-5f);
#pragma unroll
    for (int i = 0; i < 4; i++) {
        int h = tid + i * 256;
        g_zsa[(size_t)r * H + h] = (v[i] - mean) * rstd * lg[h] + lb[h];
    }
}

// ---------------------------------------------------------------------------
// GEMM: C[M=19200, N] = A[M,1024] @ B[1024,N] + bias, 128x128x8 tile,
// 256 threads, 8x8 microtile.
//   EPI 0: plain (+bias)
//   EPI 1: exact GELU(+bias)
//   EPI 2: out[(s,b,h)] = res[r,h] + val + bias  (residual + transpose to d_out)
// ---------------------------------------------------------------------------
template <int EPI>
__global__ void __launch_bounds__(256, 2)
gemm_kernel(const float* __restrict__ A, const float* __restrict__ Bm,
            const float* __restrict__ bias, float* __restrict__ C,
            int N, const float* __restrict__ res) {
    const int K = 1024;
    __shared__ float As[8][128];
    __shared__ float Bs[8][128];

    int tid = threadIdx.x;
    int mbase = blockIdx.y * 128;
    int nbase = blockIdx.x * 128;
    int ty = tid >> 4, tx = tid & 15;
    int row0 = ty * 8, col0 = tx * 8;

    float acc[8][8];
#pragma unroll
    for (int i = 0; i < 8; i++)
#pragma unroll
        for (int j = 0; j < 8; j++) acc[i][j] = 0.f;

    int arow = tid >> 1, acol = (tid & 1) * 4;
    int brow = tid >> 5, bcol = (tid & 31) * 4;
    const float* Aptr = A + (size_t)(mbase + arow) * K + acol;
    const float* Bptr = Bm + (size_t)brow * N + nbase + bcol;

    for (int kt = 0; kt < K; kt += 8) {
        float4 af = *(const float4*)(Aptr + kt);
        float4 bf = *(const float4*)(Bptr + (size_t)kt * N);
        As[acol + 0][arow] = af.x;
        As[acol + 1][arow] = af.y;
        As[acol + 2][arow] = af.z;
        As[acol + 3][arow] = af.w;
        *(float4*)&Bs[brow][bcol] = bf;
        __syncthreads();
#pragma unroll
        for (int k = 0; k < 8; k++) {
            float a[8], bb[8];
            *(float4*)&a[0]  = *(const float4*)&As[k][row0];
            *(float4*)&a[4]  = *(const float4*)&As[k][row0 + 4];
            *(float4*)&bb[0] = *(const float4*)&Bs[k][col0];
            *(float4*)&bb[4] = *(const float4*)&Bs[k][col0 + 4];
#pragma unroll
            for (int i = 0; i < 8; i++)
#pragma unroll
                for (int j = 0; j < 8; j++)
                    acc[i][j] = fmaf(a[i], bb[j], acc[i][j]);
        }
        __syncthreads();
    }

#pragma unroll
    for (int i = 0; i < 8; i++) {
        int m = mbase + row0 + i;
#pragma unroll
        for (int j = 0; j < 8; j++) {
            int n = nbase + col0 + j;
            float val = acc[i][j] + bias[n];
            if (EPI == 0) {
                C[(size_t)m * N + n] = val;
            } else if (EPI == 1) {
                C[(size_t)m * N + n] =
                    0.5f * val * (1.f + erff(val * 0.70710678118654752440f));
            } else {
                int b_ = m / S1, s_ = m % S1;
                C[((size_t)s_ * NB + b_) * H + n] = res[(size_t)m * H + n] + val;
            }
        }
    }
}

// ---------------------------------------------------------------------------
// Attention: one block per (b,s) row; banded window (cls row = full).
// 256 threads. scores -> softmax -> weighted sum of V.
// ---------------------------------------------------------------------------
__global__ void attn_kernel() {
    __shared__ float qs[H];
    __shared__ float sc[S1];
    int r = blockIdx.x;
    int b = r / S1, s = r % S1;
    int tid = threadIdx.x, lane = tid & 31, wid = tid >> 5;

    const float* base = g_qkv + (size_t)b * S1 * 3 * H;
    const float* qrow = base + (size_t)s * 3 * H;
    for (int h = tid; h < H; h += 256) qs[h] = qrow[h] * 0.03125f;  // 1/sqrt(1024)

    int lo, hi;
    if (s == 0) { lo = 0; hi = S1; }
    else {
        lo = s - WIN; if (lo < 0) lo = 0;
        hi = s + WIN; if (hi > S1) hi = S1;
    }
    __syncthreads();

    // scores: one warp per key
    for (int t = lo + wid; t < hi; t += 8) {
        const float* krow = base + (size_t)t * 3 * H + H;
        float p = 0.f;
        for (int h = lane; h < H; h += 32) p += qs[h] * krow[h];
#pragma unroll
        for (int o = 16; o; o >>= 1) p += __shfl_xor_sync(0xffffffffu, p, o);
        if (lane == 0) sc[t - lo] = p;
    }
    __syncthreads();

    // softmax on warp 0
    int n = hi - lo;
    if (tid < 32) {
        float m = -1e30f;
        for (int i = lane; i < n; i += 32) m = fmaxf(m, sc[i]);
#pragma unroll
        for (int o = 16; o; o >>= 1) m = fmaxf(m, __shfl_xor_sync(0xffffffffu, m, o));
        float ss = 0.f;
        for (int i = lane; i < n; i += 32) {
            float e = expf(sc[i] - m);
            sc[i] = e; ss += e;
        }
#pragma unroll
        for (int o = 16; o; o >>= 1) ss += __shfl_xor_sync(0xffffffffu, ss, o);
        float inv = 1.f / ss;
        for (int i = lane; i < n; i += 32) sc[i] *= inv;
    }
    __syncthreads();

    // weighted sum of V rows
    for (int h = tid; h < H; h += 256) {
        float acc = 0.f;
        const float* vcol = base + 2 * H + h;
        for (int t = lo; t < hi; t++)
            acc += sc[t - lo] * vcol[(size_t)t * 3 * H];
        g_att[(size_t)r * H + h] = acc;
    }
}

// ---------------------------------------------------------------------------
// Launch
// ---------------------------------------------------------------------------
extern "C" void kernel_launch(void* const* d_in, const int* in_sizes, int n_in,
                              void* d_out, int out_size) {
    (void)in_sizes; (void)n_in; (void)out_size;
    const float* z     = (const float*)d_in[0];
    const float* cls   = (const float*)d_in[1];
    const float* ln_g  = (const float*)d_in[2];
    const float* ln_b  = (const float*)d_in[3];
    const float* w_qkv = (const float*)d_in[4];
    const float* b_qkv = (const float*)d_in[5];
    const float* w_o   = (const float*)d_in[6];
    const float* b_o   = (const float*)d_in[7];
    const float* w_m1  = (const float*)d_in[8];
    const float* b_m1  = (const float*)d_in[9];
    const float* w_m2  = (const float*)d_in[10];
    const float* b_m2  = (const float*)d_in[11];
    float* out = (float*)d_out;

    float *px, *pqkv, *patt, *psa, *pzsa, *ph1;
    cudaGetSymbolAddress((void**)&px,   g_x);
    cudaGetSymbolAddress((void**)&pqkv, g_qkv);
    cudaGetSymbolAddress((void**)&patt, g_att);
    cudaGetSymbolAddress((void**)&psa,  g_sa);
    cudaGetSymbolAddress((void**)&pzsa, g_zsa);
    cudaGetSymbolAddress((void**)&ph1,  g_h1);

    pe_kernel<<<S1, 256>>>();
    build_ln_kernel<<<NR, 256>>>(z, cls, ln_g, ln_b);

    // qkv = x @ w_qkv + b_qkv          (19200 x 1024 x 3072)
    gemm_kernel<0><<<dim3(3 * H / 128, NR / 128), 256>>>(px, w_qkv, b_qkv, pqkv, 3 * H, nullptr);

    attn_kernel<<<NR, 256>>>();

    // sa = att @ w_o + b_o             (19200 x 1024 x 1024)
    gemm_kernel<0><<<dim3(H / 128, NR / 128), 256>>>(patt, w_o, b_o, psa, H, nullptr);

    res_ln_kernel<<<NR, 256>>>(ln_g, ln_b);

    // h1 = gelu(zsa @ w_m1 + b_m1)
    gemm_kernel<1><<<dim3(H / 128, NR / 128), 256>>>(pzsa, w_m1, b_m1, ph1, H, nullptr);

    // out = transpose(zsa + h1 @ w_m2 + b_m2)
    gemm_kernel<2><<<dim3(H / 128, NR / 128), 256>>>(ph1, w_m2, b_m2, out, H, pzsa);
}